// round 13
// baseline (speedup 1.0000x reference)
#include <cuda_runtime.h>
#include <cuda_fp16.h>
#include <mma.h>

using namespace nvcuda;

#define IN_F   4096
#define OUT_F  4096
#define RANK   64
#define M_ROWS 8192

__device__ __half g_win [RANK * IN_F];        // [64][4096] f16
__device__ __half g_wout[OUT_F * RANK];       // [4096][64] f16
__device__ float  g_xp32[2 * M_ROWS * RANK];  // K-split partials, f32 (4MB, L2-resident)
__device__ int    g_flags[64];                // per-128-row readiness (4 arrivals each)

// ---------------------------------------------------------------------------
// helpers
// ---------------------------------------------------------------------------
__device__ __forceinline__ void cp_async16(void* smem_dst, const void* gsrc) {
    unsigned s = (unsigned)__cvta_generic_to_shared(smem_dst);
    asm volatile("cp.async.cg.shared.global [%0], [%1], 16;\n" :: "r"(s), "l"(gsrc));
}
__device__ __forceinline__ void cp_async_commit() {
    asm volatile("cp.async.commit_group;\n");
}
template <int N>
__device__ __forceinline__ void cp_async_wait() {
    asm volatile("cp.async.wait_group %0;\n" :: "n"(N));
}

__device__ __forceinline__ void soft_threshold4(float4 w, float s,
                                                float& o0, float& o1, float& o2, float& o3) {
    float m0 = fabsf(w.x), m1 = fabsf(w.y), m2 = fabsf(w.z), m3 = fabsf(w.w);
    float lo01 = fminf(m0, m1), hi01 = fmaxf(m0, m1);
    float lo23 = fminf(m2, m3), hi23 = fmaxf(m2, m3);
    float t = fminf(fmaxf(lo01, lo23), fminf(hi01, hi23));  // 2nd-smallest
    o0 = copysignf(fmaxf(m0 - t, 0.0f), w.x) * s;
    o1 = copysignf(fmaxf(m1 - t, 0.0f), w.y) * s;
    o2 = copysignf(fmaxf(m2 - t, 0.0f), w.z) * s;
    o3 = copysignf(fmaxf(m3 - t, 0.0f), w.w) * s;
}

// ---------------------------------------------------------------------------
// Weight prep: threshold+scale -> g_win, g_wout; also resets g_flags
// ---------------------------------------------------------------------------
__global__ void prep_weights_kernel(const float* __restrict__ win,
                                    const float* __restrict__ wout,
                                    const float* __restrict__ scale_in,
                                    const float* __restrict__ scale_out) {
    if (blockIdx.x == 0 && threadIdx.x < 64) g_flags[threadIdx.x] = 0;

    const int NGI = RANK * IN_F / 4;    // 65536
    const int NGO = OUT_F * RANK / 4;   // 65536
    int idx = blockIdx.x * blockDim.x + threadIdx.x;
    if (idx < NGI) {
        float4 w = reinterpret_cast<const float4*>(win)[idx];
        float o0, o1, o2, o3;
        soft_threshold4(w, __ldg(scale_in), o0, o1, o2, o3);
        __half2* dst = reinterpret_cast<__half2*>(g_win) + idx * 2;
        dst[0] = __floats2half2_rn(o0, o1);
        dst[1] = __floats2half2_rn(o2, o3);
    } else if (idx < NGI + NGO) {
        int j = idx - NGI;
        float4 w = reinterpret_cast<const float4*>(wout)[j];
        float o0, o1, o2, o3;
        soft_threshold4(w, __ldg(scale_out), o0, o1, o2, o3);
        __half2* dst = reinterpret_cast<__half2*>(g_wout) + j * 2;
        dst[0] = __floats2half2_rn(o0, o1);
        dst[1] = __floats2half2_rn(o2, o3);
    }
}

// ---------------------------------------------------------------------------
// Merged producer/consumer kernel.
//   bids 0..255    : GEMM1 (K-split x2, BM=64) -> g_xp32 partials + flag arrive
//   bids 256..2303 : GEMM2 (BM=128, BN=128): spin on flag, combine xp32 halves
//                    on load, mma K=64, bias-fragment epilogue, direct store.
// ---------------------------------------------------------------------------
#define G1_LDA 72    // half, padded
#define G2_LD  72    // half, padded (K=64)
#define G2_LDB 136   // bias_rep row stride (floats)
#define N_G1_CTAS 256
// smem: gemm1 needs 4*64*72*2 = 36864; gemm2 needs 2*128*72*2 + 16*136*4 = 45568
#define SM_BYTES 45568

__global__ __launch_bounds__(256, 2)
void fused_pipeline_kernel(const float* __restrict__ x,
                           const float* __restrict__ bias,
                           float* __restrict__ out) {
    extern __shared__ __half sm[];
    const int tid  = threadIdx.x;
    const int warp = tid >> 5;
    const int bid  = blockIdx.x;

    if (bid < N_G1_CTAS) {
        // ======================= GEMM1 (producer) =======================
        __half* A0 = sm;                   // [64][72]
        __half* A1 = sm + 64 * G1_LDA;
        __half* B0 = sm + 2 * 64 * G1_LDA;
        __half* B1 = sm + 3 * 64 * G1_LDA;

        const int wm = warp & 3;   // 16 rows
        const int wn = warp >> 2;  // 32 cols
        const int m64 = bid >> 1;          // 0..127
        const int ks  = bid & 1;
        const int m0  = m64 * 64;
        const int k0  = ks * (IN_F / 2);

        wmma::fragment<wmma::accumulator, 16, 16, 16, float> acc[2];
        wmma::fill_fragment(acc[0], 0.0f);
        wmma::fill_fragment(acc[1], 0.0f);

        const int NK = (IN_F / 2) / 64;  // 32

        float4 xa0[4], xa1[4];
        int4   wb0[2], wb1[2];

        auto ldx = [&](float4* xa, int kt) {
            #pragma unroll
            for (int it = 0; it < 4; it++) {
                int i = tid + it * 256;
                int row = i >> 4, c4 = i & 15;
                xa[it] = __ldcs(reinterpret_cast<const float4*>(
                    &x[(size_t)(m0 + row) * IN_F + k0 + kt * 64 + c4 * 4]));
            }
        };
        auto ldw = [&](int4* wb, int kt) {
            #pragma unroll
            for (int it = 0; it < 2; it++) {
                int i = tid + it * 256;
                int row = i >> 3, c8 = i & 7;
                wb[it] = *reinterpret_cast<const int4*>(
                    &g_win[row * IN_F + k0 + kt * 64 + c8 * 8]);
            }
        };
        auto stage = [&](__half* A, __half* B, const float4* xa, const int4* wb) {
            #pragma unroll
            for (int it = 0; it < 4; it++) {
                int i = tid + it * 256;
                int row = i >> 4, c4 = i & 15;
                __half* p = &A[row * G1_LDA + c4 * 4];
                reinterpret_cast<__half2*>(p)[0] = __floats2half2_rn(xa[it].x, xa[it].y);
                reinterpret_cast<__half2*>(p)[1] = __floats2half2_rn(xa[it].z, xa[it].w);
            }
            #pragma unroll
            for (int it = 0; it < 2; it++) {
                int i = tid + it * 256;
                int row = i >> 3, c8 = i & 7;
                *reinterpret_cast<int4*>(&B[row * G1_LDA + c8 * 8]) = wb[it];
            }
        };
        auto mma = [&](const __half* A, const __half* B) {
            #pragma unroll
            for (int k4 = 0; k4 < 4; k4++) {
                wmma::fragment<wmma::matrix_a, 16, 16, 16, __half, wmma::row_major> a;
                wmma::load_matrix_sync(a, &A[(wm * 16) * G1_LDA + k4 * 16], G1_LDA);
                #pragma unroll
                for (int j = 0; j < 2; j++) {
                    wmma::fragment<wmma::matrix_b, 16, 16, 16, __half, wmma::col_major> b;
                    wmma::load_matrix_sync(b, &B[(wn * 32 + j * 16) * G1_LDA + k4 * 16], G1_LDA);
                    wmma::mma_sync(acc[j], a, b, acc[j]);
                }
            }
        };

        ldx(xa0, 0); ldw(wb0, 0);
        ldx(xa1, 1); ldw(wb1, 1);

        for (int kt = 0; kt < NK; kt += 2) {
            stage(A0, B0, xa0, wb0);
            __syncthreads();
            if (kt + 2 < NK) { ldx(xa0, kt + 2); ldw(wb0, kt + 2); }
            mma(A0, B0);

            stage(A1, B1, xa1, wb1);
            __syncthreads();
            if (kt + 3 < NK) { ldx(xa1, kt + 3); ldw(wb1, kt + 3); }
            mma(A1, B1);
        }

        float* outp = g_xp32 + (size_t)ks * M_ROWS * RANK;
        #pragma unroll
        for (int j = 0; j < 2; j++)
            wmma::store_matrix_sync(&outp[(size_t)(m0 + wm * 16) * RANK + wn * 32 + j * 16],
                                    acc[j], RANK, wmma::mem_row_major);

        __syncthreads();
        if (tid == 0) {
            __threadfence();
            atomicAdd(&g_flags[m64 >> 1], 1);
        }
    } else {
        // ======================= GEMM2 (consumer) =======================
        __half* Ps = sm;                  // [128][72]
        __half* Ws = sm + 128 * G2_LD;    // [128][72]
        float* bias_rep = reinterpret_cast<float*>(sm + 2 * 128 * G2_LD);  // [16][136]

        const int b2 = bid - N_G1_CTAS;   // 0..2047
        const int mc = b2 >> 5;           // 0..63  (m-chunk of 128 rows)
        const int nt = b2 & 31;           // 0..31
        const int m0 = mc * 128;
        const int n0 = nt * 128;
        const int wm = warp & 3;   // 32 rows
        const int wn = warp >> 2;  // 64 cols

        // Ws tile (ready — prep ran in prior launch); lands during the spin
        #pragma unroll
        for (int it = 0; it < 4; it++) {
            int c = tid + it * 256;
            int row = c >> 3, off = c & 7;
            cp_async16(Ws + row * G2_LD + off * 8,
                       g_wout + (size_t)(n0 + row) * RANK + off * 8);
        }
        cp_async_commit();

        // bias_rep: 128 cols replicated over 16 rows
        if (tid < 128) {
            float bv = __ldg(&bias[n0 + tid]);
            #pragma unroll
            for (int r = 0; r < 16; r++) bias_rep[r * G2_LDB + tid] = bv;
        }

        // wait for both K-split halves of both 64-row blocks of this chunk
        if (tid == 0) {
            while (atomicAdd(&g_flags[mc], 0) < 4) __nanosleep(128);
        }
        __syncthreads();

        // combine xp32 halves -> Ps (f16). 128 rows x 16 float4 = 2048 / 256 thr
        const float* h0 = g_xp32;
        const float* h1 = g_xp32 + (size_t)M_ROWS * RANK;
        #pragma unroll
        for (int it = 0; it < 8; it++) {
            int c = tid + it * 256;
            int row = c >> 4, c4 = c & 15;
            size_t gi = (size_t)(m0 + row) * RANK + c4 * 4;
            float4 a = __ldcg(reinterpret_cast<const float4*>(h0 + gi));
            float4 b = __ldcg(reinterpret_cast<const float4*>(h1 + gi));
            __half2* p = reinterpret_cast<__half2*>(&Ps[row * G2_LD + c4 * 4]);
            p[0] = __floats2half2_rn(a.x + b.x, a.y + b.y);
            p[1] = __floats2half2_rn(a.z + b.z, a.w + b.w);
        }

        cp_async_wait<0>();
        __syncthreads();

        wmma::fragment<wmma::accumulator, 16, 16, 16, float> acc[2][4];
        #pragma unroll
        for (int i = 0; i < 2; i++)
            #pragma unroll
            for (int j = 0; j < 4; j++) wmma::fill_fragment(acc[i][j], 0.0f);

        #pragma unroll
        for (int k4 = 0; k4 < 4; k4++) {   // K = 64
            wmma::fragment<wmma::matrix_a, 16, 16, 16, __half, wmma::row_major> a[2];
            #pragma unroll
            for (int i = 0; i < 2; i++)
                wmma::load_matrix_sync(a[i], &Ps[(wm * 32 + i * 16) * G2_LD + k4 * 16], G2_LD);
            #pragma unroll
            for (int j = 0; j < 4; j++) {
                wmma::fragment<wmma::matrix_b, 16, 16, 16, __half, wmma::col_major> b;
                wmma::load_matrix_sync(b, &Ws[(wn * 64 + j * 16) * G2_LD + k4 * 16], G2_LD);
                #pragma unroll
                for (int i = 0; i < 2; i++)
                    wmma::mma_sync(acc[i][j], a[i], b, acc[i][j]);
            }
        }

        const float scaling = 1.0f / (float)RANK;
        #pragma unroll
        for (int i = 0; i < 2; i++)
            #pragma unroll
            for (int j = 0; j < 4; j++) {
                wmma::fragment<wmma::accumulator, 16, 16, 16, float> bf;
                wmma::load_matrix_sync(bf, &bias_rep[wn * 64 + j * 16], G2_LDB,
                                       wmma::mem_row_major);
                #pragma unroll
                for (int e = 0; e < acc[i][j].num_elements; e++)
                    acc[i][j].x[e] = (acc[i][j].x[e] + bf.x[e]) * scaling;
                wmma::store_matrix_sync(
                    &out[(size_t)(m0 + wm * 32 + i * 16) * OUT_F + n0 + wn * 64 + j * 16],
                    acc[i][j], OUT_F, wmma::mem_row_major);
            }
    }
}

// ---------------------------------------------------------------------------
// Launcher
// ---------------------------------------------------------------------------
extern "C" void kernel_launch(void* const* d_in, const int* in_sizes, int n_in,
                              void* d_out, int out_size) {
    const float* x         = (const float*)d_in[0];
    const float* weight_in = (const float*)d_in[1];
    const float* weight_out= (const float*)d_in[2];
    const float* bias      = (const float*)d_in[3];
    const float* scale_in  = (const float*)d_in[4];
    const float* scale_out = (const float*)d_in[5];
    float* out = (float*)d_out;

    const int M = in_sizes[0] / IN_F;  // 8192

    {
        int total = RANK * IN_F / 4 + OUT_F * RANK / 4;   // 131072
        prep_weights_kernel<<<(total + 255) / 256, 256>>>(
            weight_in, weight_out, scale_in, scale_out);
    }
    {
        int n_ctas = N_G1_CTAS + (M / 128) * (OUT_F / 128);  // 256 + 2048
        fused_pipeline_kernel<<<n_ctas, 256, SM_BYTES>>>(x, bias, out);
    }
}